// round 7
// baseline (speedup 1.0000x reference)
#include <cuda_runtime.h>
#include <cuda_fp16.h>
#include <cstdint>

#define D 128
#define MAXN 100000
#define MAXE 1600000

// Scratch (allocation-free rule: __device__ globals) — fp16 activations
__device__ __align__(16) __half g_xh[(size_t)MAXN * D];
__device__ __align__(16) __half g_oh[(size_t)MAXN * D];
__device__ __align__(16) __half g_wh[4 * D * D];   // weights [c][k] fp16
__device__ int g_deg[MAXN];
__device__ int g_incl[MAXN];
__device__ int g_bsum[128];
__device__ int g_boff[128];
__device__ int g_rowptr[MAXN + 1];
__device__ int g_cursor[MAXN];
__device__ int g_elist[MAXE];

// ---------------------------------------------------------------------------
__global__ void convert_w_kernel(const float* __restrict__ w0,
                                 const float* __restrict__ w1,
                                 const float* __restrict__ w2,
                                 const float* __restrict__ w3) {
    int i = blockIdx.x * blockDim.x + threadIdx.x;
    if (i >= 4 * D * D) return;
    int widx = i >> 14;
    const float* w = (widx == 0) ? w0 : (widx == 1) ? w1 : (widx == 2) ? w2 : w3;
    g_wh[i] = __float2half(w[i & 16383]);
}

__global__ void convert_x_kernel(const float* __restrict__ x, int n4) {
    int i = blockIdx.x * blockDim.x + threadIdx.x;
    if (i >= n4) return;
    float4 v = __ldg((const float4*)x + i);
    __half2 h0 = __floats2half2_rn(v.x, v.y);
    __half2 h1 = __floats2half2_rn(v.z, v.w);
    uint2 u;
    u.x = *(unsigned*)&h0;
    u.y = *(unsigned*)&h1;
    ((uint2*)g_xh)[i] = u;
}

// ---------------------------------------------------------------------------
// CSR build
__global__ void zero_deg_kernel(int n) {
    int i = blockIdx.x * blockDim.x + threadIdx.x;
    if (i < n) g_deg[i] = 0;
}

__global__ void hist_kernel(const int* __restrict__ ei, int E) {
    int t = blockIdx.x * blockDim.x + threadIdx.x;
    int base = t * 4;
    if (base + 4 <= E) {
        int4 d = __ldg((const int4*)(ei + E) + t);
        atomicAdd(&g_deg[d.x], 1);
        atomicAdd(&g_deg[d.y], 1);
        atomicAdd(&g_deg[d.z], 1);
        atomicAdd(&g_deg[d.w], 1);
    } else {
        for (int e = base; e < E; e++) atomicAdd(&g_deg[__ldg(ei + E + e)], 1);
    }
}

__global__ void scan1_kernel(int n) {
    __shared__ int wsum[32];
    int t = threadIdx.x, b = blockIdx.x;
    int i = b * 1024 + t;
    int lane = t & 31, warp = t >> 5;
    int v = (i < n) ? g_deg[i] : 0;
    int s = v;
#pragma unroll
    for (int off = 1; off < 32; off <<= 1) {
        int u = __shfl_up_sync(0xffffffffu, s, off);
        if (lane >= off) s += u;
    }
    if (lane == 31) wsum[warp] = s;
    __syncthreads();
    if (warp == 0) {
        int ws = wsum[lane];
#pragma unroll
        for (int off = 1; off < 32; off <<= 1) {
            int u = __shfl_up_sync(0xffffffffu, ws, off);
            if (lane >= off) ws += u;
        }
        wsum[lane] = ws;
    }
    __syncthreads();
    int incl = s + (warp > 0 ? wsum[warp - 1] : 0);
    if (i < n) g_incl[i] = incl;
    if (t == 1023) g_bsum[b] = incl;
}

__global__ void scan2_kernel(int nb) {
    __shared__ int s[128];
    int t = threadIdx.x;
    int v = (t < nb) ? g_bsum[t] : 0;
    s[t] = v;
    __syncthreads();
#pragma unroll
    for (int off = 1; off < 128; off <<= 1) {
        int u = (t >= off) ? s[t - off] : 0;
        __syncthreads();
        s[t] += u;
        __syncthreads();
    }
    g_boff[t] = s[t] - v;
}

__global__ void scan3_kernel(int n, int E) {
    int i = blockIdx.x * blockDim.x + threadIdx.x;
    if (i < n) {
        int excl = g_boff[i >> 10] + g_incl[i] - g_deg[i];
        g_rowptr[i] = excl;
        g_cursor[i] = excl;
    }
    if (i == 0) g_rowptr[n] = E;
}

__global__ void fill_kernel(const int* __restrict__ ei, int E) {
    int t = blockIdx.x * blockDim.x + threadIdx.x;
    int base = t * 4;
    if (base + 4 <= E) {
        int4 s = __ldg((const int4*)ei + t);
        int4 d = __ldg((const int4*)(ei + E) + t);
        g_elist[atomicAdd(&g_cursor[d.x], 1)] = s.x;
        g_elist[atomicAdd(&g_cursor[d.y], 1)] = s.y;
        g_elist[atomicAdd(&g_cursor[d.z], 1)] = s.z;
        g_elist[atomicAdd(&g_cursor[d.w], 1)] = s.w;
    } else {
        for (int e = base; e < E; e++) {
            int s = __ldg(ei + e);
            int d = __ldg(ei + E + e);
            g_elist[atomicAdd(&g_cursor[d], 1)] = s;
        }
    }
}

// ---------------------------------------------------------------------------
// Fused layer (warp-specialized):
//   out = relu((X_agg) @ W1^T + b1) @ W2^T + b2
// where X_agg[n] = x[n] + sum_{s in N(n)} x[s] is produced on the fly.
// Warps 0-3: producers (CSR gather -> smem tile ring). Warps 4-7: consumers
// (dual MMA, T stays in registers via C-frag == A-frag identity).
#define XSTR 136
#define WSTR 136
#define TR 64
#define NSLOT 2

#define BAR_SYNC(id)   asm volatile("bar.sync %0, %1;"   :: "r"(id), "r"(256) : "memory")
#define BAR_ARRIVE(id) asm volatile("bar.arrive %0, %1;" :: "r"(id), "r"(256) : "memory")
// FULL slot s -> id 1+s ; EMPTY slot s -> id 3+s

__device__ __forceinline__ void mma_16x8x16(float* d, const unsigned* a, const unsigned* b) {
    asm volatile(
        "mma.sync.aligned.m16n8k16.row.col.f32.f16.f16.f32 "
        "{%0,%1,%2,%3}, {%4,%5,%6,%7}, {%8,%9}, {%0,%1,%2,%3};"
        : "+f"(d[0]), "+f"(d[1]), "+f"(d[2]), "+f"(d[3])
        : "r"(a[0]), "r"(a[1]), "r"(a[2]), "r"(a[3]), "r"(b[0]), "r"(b[1]));
}

__device__ __forceinline__ void facc(float4& a, uint2 u) {
    float2 f0 = __half22float2(*(__half2*)&u.x);
    float2 f1 = __half22float2(*(__half2*)&u.y);
    a.x += f0.x; a.y += f0.y; a.z += f1.x; a.w += f1.y;
}

__global__ __launch_bounds__(256, 1)
void layer_ws_kernel(const __half* __restrict__ xin,    // gather source
                     const __half* __restrict__ w1,     // [c][k]
                     const float* __restrict__ b1,
                     const __half* __restrict__ w2,     // [c][k]
                     const float* __restrict__ b2,
                     __half* __restrict__ outh,
                     float* __restrict__ outf,
                     int nrows) {
    extern __shared__ __half smh[];
    __half* Ws1 = smh;                         // [128][WSTR]
    __half* Ws2 = smh + 128 * WSTR;            // [128][WSTR]
    __half* Xs  = smh + 2 * 128 * WSTR;        // [NSLOT][TR][XSTR]

    int tid = threadIdx.x;
    int warp = tid >> 5, lane = tid & 31;

    // All threads load W panels
    for (int i = tid; i < 128 * 16; i += 256) {
        int c = i >> 4, seg = i & 15;
        *(uint4*)(Ws1 + c * WSTR + seg * 8) = __ldg((const uint4*)w1 + i);
        *(uint4*)(Ws2 + c * WSTR + seg * 8) = __ldg((const uint4*)w2 + i);
    }
    __syncthreads();

    int ntiles = (nrows + TR - 1) / TR;
    int stride = gridDim.x;

    if (warp < 4) {
        // ---------------- PRODUCER: gather 16 nodes per warp per tile ------
        const uint2* x2 = (const uint2*)xin;
        int it = 0;
        for (int tt = blockIdx.x; tt < ntiles; tt += stride, it++) {
            int s = it & 1;
            if (it >= NSLOT) BAR_SYNC(3 + s);
            __half* Xbuf = Xs + s * TR * XSTR + (warp * 16) * XSTR;
            long long n0 = (long long)tt * TR + warp * 16;
            for (int n = 0; n < 16; n++) {
                long long node = n0 + n;
                float4 acc = make_float4(0.f, 0.f, 0.f, 0.f);
                if (node < nrows) {
                    facc(acc, __ldg(x2 + node * 32 + lane));
                    int beg = __ldg(g_rowptr + node);
                    int end = __ldg(g_rowptr + node + 1);
                    int i = beg;
                    for (; i + 8 <= end; i += 8) {
                        uint2 v0 = __ldg(x2 + (long long)__ldg(g_elist + i)     * 32 + lane);
                        uint2 v1 = __ldg(x2 + (long long)__ldg(g_elist + i + 1) * 32 + lane);
                        uint2 v2 = __ldg(x2 + (long long)__ldg(g_elist + i + 2) * 32 + lane);
                        uint2 v3 = __ldg(x2 + (long long)__ldg(g_elist + i + 3) * 32 + lane);
                        uint2 v4 = __ldg(x2 + (long long)__ldg(g_elist + i + 4) * 32 + lane);
                        uint2 v5 = __ldg(x2 + (long long)__ldg(g_elist + i + 5) * 32 + lane);
                        uint2 v6 = __ldg(x2 + (long long)__ldg(g_elist + i + 6) * 32 + lane);
                        uint2 v7 = __ldg(x2 + (long long)__ldg(g_elist + i + 7) * 32 + lane);
                        facc(acc, v0); facc(acc, v1); facc(acc, v2); facc(acc, v3);
                        facc(acc, v4); facc(acc, v5); facc(acc, v6); facc(acc, v7);
                    }
                    for (; i < end; i++)
                        facc(acc, __ldg(x2 + (long long)__ldg(g_elist + i) * 32 + lane));
                }
                __half2 h0 = __floats2half2_rn(acc.x, acc.y);
                __half2 h1 = __floats2half2_rn(acc.z, acc.w);
                uint2 u;
                u.x = *(unsigned*)&h0;
                u.y = *(unsigned*)&h1;
                *(uint2*)(Xbuf + n * XSTR + lane * 4) = u;
            }
            __threadfence_block();
            BAR_ARRIVE(1 + s);
        }
    } else {
        // ---------------- CONSUMER: dual MMA on 16-row stripe --------------
        int wp = warp - 4;
        int gi = lane >> 2, ti = lane & 3;
        int mbase = wp * 16;
        int it = 0;
        for (int tt = blockIdx.x; tt < ntiles; tt += stride, it++) {
            int s = it & 1;
            BAR_SYNC(1 + s);
            const __half* Xt = Xs + s * TR * XSTR;

            // MMA1: T[16][128]
            float acc1[16][4];
#pragma unroll
            for (int j = 0; j < 16; j++)
#pragma unroll
                for (int q = 0; q < 4; q++) acc1[j][q] = 0.f;

#pragma unroll
            for (int kk = 0; kk < 8; kk++) {
                int k0 = kk * 16;
                unsigned a[4];
                int r = mbase + gi;
                a[0] = *(const unsigned*)(Xt + r * XSTR + k0 + 2 * ti);
                a[1] = *(const unsigned*)(Xt + (r + 8) * XSTR + k0 + 2 * ti);
                a[2] = *(const unsigned*)(Xt + r * XSTR + k0 + 2 * ti + 8);
                a[3] = *(const unsigned*)(Xt + (r + 8) * XSTR + k0 + 2 * ti + 8);
#pragma unroll
                for (int j = 0; j < 16; j++) {
                    int c = j * 8 + gi;
                    unsigned b[2];
                    b[0] = *(const unsigned*)(Ws1 + c * WSTR + k0 + 2 * ti);
                    b[1] = *(const unsigned*)(Ws1 + c * WSTR + k0 + 2 * ti + 8);
                    mma_16x8x16(acc1[j], a, b);
                }
            }
            BAR_ARRIVE(3 + s);   // done reading slot s

            // bias1 + relu + C->A fragment conversion
            unsigned af[16][2];
#pragma unroll
            for (int j = 0; j < 16; j++) {
                int c0 = j * 8 + 2 * ti;
                float2 bb = __ldg((const float2*)(b1 + c0));
                float v0 = fmaxf(acc1[j][0] + bb.x, 0.f);
                float v1 = fmaxf(acc1[j][1] + bb.y, 0.f);
                float v2 = fmaxf(acc1[j][2] + bb.x, 0.f);
                float v3 = fmaxf(acc1[j][3] + bb.y, 0.f);
                __half2 lo = __floats2half2_rn(v0, v1);
                __half2 hi = __floats2half2_rn(v2, v3);
                af[j][0] = *(unsigned*)&lo;
                af[j][1] = *(unsigned*)&hi;
            }

            // MMA2
            float acc2[16][4];
#pragma unroll
            for (int j = 0; j < 16; j++)
#pragma unroll
                for (int q = 0; q < 4; q++) acc2[j][q] = 0.f;

#pragma unroll
            for (int kk = 0; kk < 8; kk++) {
                int k0 = kk * 16;
                unsigned a[4] = {af[2 * kk][0], af[2 * kk][1],
                                 af[2 * kk + 1][0], af[2 * kk + 1][1]};
#pragma unroll
                for (int j = 0; j < 16; j++) {
                    int c = j * 8 + gi;
                    unsigned b[2];
                    b[0] = *(const unsigned*)(Ws2 + c * WSTR + k0 + 2 * ti);
                    b[1] = *(const unsigned*)(Ws2 + c * WSTR + k0 + 2 * ti + 8);
                    mma_16x8x16(acc2[j], a, b);
                }
            }

            // epilogue
            long long row0 = (long long)tt * TR + mbase + gi;
#pragma unroll
            for (int j = 0; j < 16; j++) {
                int c0 = j * 8 + 2 * ti;
                float2 bb = __ldg((const float2*)(b2 + c0));
                float v0 = acc2[j][0] + bb.x;
                float v1 = acc2[j][1] + bb.y;
                float v2 = acc2[j][2] + bb.x;
                float v3 = acc2[j][3] + bb.y;
                if (outf) {
                    if (row0 < nrows)
                        *(float2*)(outf + row0 * D + c0) = make_float2(v0, v1);
                    if (row0 + 8 < nrows)
                        *(float2*)(outf + (row0 + 8) * D + c0) = make_float2(v2, v3);
                } else {
                    if (row0 < nrows)
                        *(__half2*)(outh + row0 * D + c0) = __floats2half2_rn(v0, v1);
                    if (row0 + 8 < nrows)
                        *(__half2*)(outh + (row0 + 8) * D + c0) = __floats2half2_rn(v2, v3);
                }
            }
        }
    }
}

// ---------------------------------------------------------------------------
extern "C" void kernel_launch(void* const* d_in, const int* in_sizes, int n_in,
                              void* d_out, int out_size) {
    const float* x   = (const float*)d_in[0];
    const int*   ei  = (const int*)d_in[1];
    const float* w0a = (const float*)d_in[2];
    const float* b0a = (const float*)d_in[3];
    const float* w0b = (const float*)d_in[4];
    const float* b0b = (const float*)d_in[5];
    const float* w1a = (const float*)d_in[6];
    const float* b1a = (const float*)d_in[7];
    const float* w1b = (const float*)d_in[8];
    const float* b1b = (const float*)d_in[9];

    int N = in_sizes[0] / D;
    int E = in_sizes[1] / 2;

    __half *p_xh, *p_oh, *p_wh;
    cudaGetSymbolAddress((void**)&p_xh, g_xh);
    cudaGetSymbolAddress((void**)&p_oh, g_oh);
    cudaGetSymbolAddress((void**)&p_wh, g_wh);

    int nsm = 148;
    cudaDeviceGetAttribute(&nsm, cudaDevAttrMultiProcessorCount, 0);

    const int smem = (2 * 128 * WSTR + NSLOT * TR * XSTR) * (int)sizeof(__half);
    cudaFuncSetAttribute(layer_ws_kernel, cudaFuncAttributeMaxDynamicSharedMemorySize, smem);

    int nb = (N + 1023) / 1024;
    int n4 = N * (D / 4);
    int e4 = (E + 3) / 4;

    convert_w_kernel<<<(4 * D * D + 255) / 256, 256>>>(w0a, w0b, w1a, w1b);
    convert_x_kernel<<<(n4 + 255) / 256, 256>>>(x, n4);

    // ---- CSR build ----
    zero_deg_kernel<<<(N + 255) / 256, 256>>>(N);
    hist_kernel<<<(e4 + 255) / 256, 256>>>(ei, E);
    scan1_kernel<<<nb, 1024>>>(N);
    scan2_kernel<<<1, 128>>>(nb);
    scan3_kernel<<<(N + 255) / 256, 256>>>(N, E);
    fill_kernel<<<(e4 + 255) / 256, 256>>>(ei, E);

    // ---- Layer 1 (gather from x, output fp16) ----
    layer_ws_kernel<<<nsm, 256, smem>>>(p_xh, p_wh + 0 * D * D, b0a,
                                        p_wh + 1 * D * D, b0b, p_oh, nullptr, N);
    // ---- Layer 2 (gather from layer-1 output, output fp32 to d_out) ----
    layer_ws_kernel<<<nsm, 256, smem>>>(p_oh, p_wh + 2 * D * D, b1a,
                                        p_wh + 3 * D * D, b1b, nullptr, (float*)d_out, N);
}

// round 8
// speedup vs baseline: 2.8704x; 2.8704x over previous
#include <cuda_runtime.h>
#include <cuda_fp16.h>
#include <cstdint>

#define D 128
#define MAXN 100000
#define MAXE 1600000

// Scratch (allocation-free rule: __device__ globals) — fp16 activations
__device__ __align__(16) __half g_xh[(size_t)MAXN * D];
__device__ __align__(16) __half g_hh[(size_t)MAXN * D];
__device__ __align__(16) __half g_oh[(size_t)MAXN * D];
__device__ __align__(16) __half g_wh[4 * D * D];   // weights [c][k] fp16
__device__ int g_deg[MAXN];
__device__ int g_incl[MAXN];
__device__ int g_bsum[128];
__device__ int g_boff[128];
__device__ int g_rowptr[MAXN + 1];
__device__ int g_cursor[MAXN];
__device__ int g_elist[MAXE];

// ---------------------------------------------------------------------------
__global__ void convert_w_kernel(const float* __restrict__ w0,
                                 const float* __restrict__ w1,
                                 const float* __restrict__ w2,
                                 const float* __restrict__ w3) {
    int i = blockIdx.x * blockDim.x + threadIdx.x;
    if (i >= 4 * D * D) return;
    int widx = i >> 14;
    const float* w = (widx == 0) ? w0 : (widx == 1) ? w1 : (widx == 2) ? w2 : w3;
    g_wh[i] = __float2half(w[i & 16383]);
}

__global__ void convert_x_kernel(const float* __restrict__ x, int n4) {
    int i = blockIdx.x * blockDim.x + threadIdx.x;
    if (i >= n4) return;
    float4 v = __ldg((const float4*)x + i);
    __half2 h0 = __floats2half2_rn(v.x, v.y);
    __half2 h1 = __floats2half2_rn(v.z, v.w);
    uint2 u;
    u.x = *(unsigned*)&h0;
    u.y = *(unsigned*)&h1;
    ((uint2*)g_xh)[i] = u;
}

// ---------------------------------------------------------------------------
// CSR build
__global__ void zero_deg_kernel(int n) {
    int i = blockIdx.x * blockDim.x + threadIdx.x;
    if (i < n) g_deg[i] = 0;
}

__global__ void hist_kernel(const int* __restrict__ ei, int E) {
    int t = blockIdx.x * blockDim.x + threadIdx.x;
    int base = t * 4;
    if (base + 4 <= E) {
        int4 d = __ldg((const int4*)(ei + E) + t);
        atomicAdd(&g_deg[d.x], 1);
        atomicAdd(&g_deg[d.y], 1);
        atomicAdd(&g_deg[d.z], 1);
        atomicAdd(&g_deg[d.w], 1);
    } else {
        for (int e = base; e < E; e++) atomicAdd(&g_deg[__ldg(ei + E + e)], 1);
    }
}

__global__ void scan1_kernel(int n) {
    __shared__ int wsum[32];
    int t = threadIdx.x, b = blockIdx.x;
    int i = b * 1024 + t;
    int lane = t & 31, warp = t >> 5;
    int v = (i < n) ? g_deg[i] : 0;
    int s = v;
#pragma unroll
    for (int off = 1; off < 32; off <<= 1) {
        int u = __shfl_up_sync(0xffffffffu, s, off);
        if (lane >= off) s += u;
    }
    if (lane == 31) wsum[warp] = s;
    __syncthreads();
    if (warp == 0) {
        int ws = wsum[lane];
#pragma unroll
        for (int off = 1; off < 32; off <<= 1) {
            int u = __shfl_up_sync(0xffffffffu, ws, off);
            if (lane >= off) ws += u;
        }
        wsum[lane] = ws;
    }
    __syncthreads();
    int incl = s + (warp > 0 ? wsum[warp - 1] : 0);
    if (i < n) g_incl[i] = incl;
    if (t == 1023) g_bsum[b] = incl;
}

__global__ void scan2_kernel(int nb) {
    __shared__ int s[128];
    int t = threadIdx.x;
    int v = (t < nb) ? g_bsum[t] : 0;
    s[t] = v;
    __syncthreads();
#pragma unroll
    for (int off = 1; off < 128; off <<= 1) {
        int u = (t >= off) ? s[t - off] : 0;
        __syncthreads();
        s[t] += u;
        __syncthreads();
    }
    g_boff[t] = s[t] - v;
}

__global__ void scan3_kernel(int n, int E) {
    int i = blockIdx.x * blockDim.x + threadIdx.x;
    if (i < n) {
        int excl = g_boff[i >> 10] + g_incl[i] - g_deg[i];
        g_rowptr[i] = excl;
        g_cursor[i] = excl;
    }
    if (i == 0) g_rowptr[n] = E;
}

__global__ void fill_kernel(const int* __restrict__ ei, int E) {
    int t = blockIdx.x * blockDim.x + threadIdx.x;
    int base = t * 4;
    if (base + 4 <= E) {
        int4 s = __ldg((const int4*)ei + t);
        int4 d = __ldg((const int4*)(ei + E) + t);
        g_elist[atomicAdd(&g_cursor[d.x], 1)] = s.x;
        g_elist[atomicAdd(&g_cursor[d.y], 1)] = s.y;
        g_elist[atomicAdd(&g_cursor[d.z], 1)] = s.z;
        g_elist[atomicAdd(&g_cursor[d.w], 1)] = s.w;
    } else {
        for (int e = base; e < E; e++) {
            int s = __ldg(ei + e);
            int d = __ldg(ei + E + e);
            g_elist[atomicAdd(&g_cursor[d], 1)] = s;
        }
    }
}

// ---------------------------------------------------------------------------
// Gather: h[n] = x[n] + sum_{s in N(n)} x[s].  fp16 in/out, fp32 accumulate.
__device__ __forceinline__ void acc_add(float4& a, uint2 u) {
    float2 f0 = __half22float2(*(__half2*)&u.x);
    float2 f1 = __half22float2(*(__half2*)&u.y);
    a.x += f0.x; a.y += f0.y; a.z += f1.x; a.w += f1.y;
}

__global__ void gather_h_kernel(const __half* __restrict__ xin,
                                __half* __restrict__ hout, int N) {
    int w = (int)((blockIdx.x * (unsigned)blockDim.x + threadIdx.x) >> 5);
    if (w >= N) return;
    int lane = threadIdx.x & 31;
    const uint2* x2 = (const uint2*)xin;
    float4 acc = make_float4(0.f, 0.f, 0.f, 0.f);
    acc_add(acc, __ldg(x2 + (long long)w * 32 + lane));
    int beg = __ldg(g_rowptr + w);
    int end = __ldg(g_rowptr + w + 1);
    int i = beg;
    for (; i + 4 <= end; i += 4) {
        int s0 = __ldg(g_elist + i);
        int s1 = __ldg(g_elist + i + 1);
        int s2 = __ldg(g_elist + i + 2);
        int s3 = __ldg(g_elist + i + 3);
        uint2 v0 = __ldg(x2 + (long long)s0 * 32 + lane);
        uint2 v1 = __ldg(x2 + (long long)s1 * 32 + lane);
        uint2 v2 = __ldg(x2 + (long long)s2 * 32 + lane);
        uint2 v3 = __ldg(x2 + (long long)s3 * 32 + lane);
        acc_add(acc, v0); acc_add(acc, v1); acc_add(acc, v2); acc_add(acc, v3);
    }
    for (; i < end; i++) {
        int s0 = __ldg(g_elist + i);
        acc_add(acc, __ldg(x2 + (long long)s0 * 32 + lane));
    }
    __half2 h0 = __floats2half2_rn(acc.x, acc.y);
    __half2 h1 = __floats2half2_rn(acc.z, acc.w);
    uint2 u;
    u.x = *(unsigned*)&h0;
    u.y = *(unsigned*)&h1;
    ((uint2*)hout)[(long long)w * 32 + lane] = u;
}

// ---------------------------------------------------------------------------
// Fused layer: out = relu(X @ W1^T + b1) @ W2^T + b2   (persistent, fp16 MMA)
// Tile 128 rows; each warp owns a 16-row stripe, all 128 cols.
// T never leaves registers (C-frag == A-frag). Fragment loads via ldmatrix.
#define XSTR 136
#define WSTR 136
#define TR 128

__device__ __forceinline__ void mma_16x8x16(float* d, const unsigned* a, const unsigned* b) {
    asm volatile(
        "mma.sync.aligned.m16n8k16.row.col.f32.f16.f16.f32 "
        "{%0,%1,%2,%3}, {%4,%5,%6,%7}, {%8,%9}, {%0,%1,%2,%3};"
        : "+f"(d[0]), "+f"(d[1]), "+f"(d[2]), "+f"(d[3])
        : "r"(a[0]), "r"(a[1]), "r"(a[2]), "r"(a[3]), "r"(b[0]), "r"(b[1]));
}

__device__ __forceinline__ void ldsm_x4(unsigned& r0, unsigned& r1,
                                        unsigned& r2, unsigned& r3, unsigned addr) {
    asm volatile("ldmatrix.sync.aligned.m8n8.x4.shared.b16 {%0,%1,%2,%3}, [%4];"
                 : "=r"(r0), "=r"(r1), "=r"(r2), "=r"(r3) : "r"(addr));
}

__global__ __launch_bounds__(256, 1)
void layer_fused_kernel(const __half* __restrict__ in,
                        const __half* __restrict__ w1,   // [c][k]
                        const float* __restrict__ b1,
                        const __half* __restrict__ w2,   // [c][k]
                        const float* __restrict__ b2,
                        __half* __restrict__ outh,
                        float* __restrict__ outf,
                        int nrows) {
    extern __shared__ __half smh[];
    __half* Ws1 = smh;                        // [128][WSTR]
    __half* Ws2 = smh + 128 * WSTR;           // [128][WSTR]
    __half* Xs0 = smh + 2 * 128 * WSTR;       // [128][XSTR]
    __half* Xs1 = Xs0 + TR * XSTR;

    int tid = threadIdx.x;

    // Load both W panels (each 128 rows x 16 uint4)
    for (int i = tid; i < 128 * 16; i += 256) {
        int c = i >> 4, seg = i & 15;
        *(uint4*)(Ws1 + c * WSTR + seg * 8) = __ldg((const uint4*)w1 + i);
        *(uint4*)(Ws2 + c * WSTR + seg * 8) = __ldg((const uint4*)w2 + i);
    }

    int warp = tid >> 5, lane = tid & 31;
    int gi = lane >> 2, ti = lane & 3;
    int mbase = warp * 16;

    // ldmatrix per-lane address offsets (in half units)
    // A x4: m0=rows mbase+0..7 @k0 | m1=rows+8 @k0 | m2=rows @k0+8 | m3=rows+8 @k0+8
    int a_row = mbase + (lane & 7) + (((lane >> 3) & 1) << 3);
    int a_koff = (lane >> 4) << 3;
    // B x4: m0=(j cols, k0) | m1=(j, k0+8) | m2=(j+1, k0) | m3=(j+1, k0+8)
    int b_row = (lane & 7) + ((lane >> 4) << 3);      // col within 16-col pair
    int b_koff = ((lane >> 3) & 1) << 3;

    unsigned ws1_base = (unsigned)__cvta_generic_to_shared(Ws1);
    unsigned ws2_base = (unsigned)__cvta_generic_to_shared(Ws2);
    unsigned xs0_base = (unsigned)__cvta_generic_to_shared(Xs0);
    unsigned xs1_base = (unsigned)__cvta_generic_to_shared(Xs1);
    unsigned b1_off = (b_row * WSTR + b_koff) * 2;    // bytes
    unsigned a_off  = (a_row * XSTR + a_koff) * 2;    // bytes

    int ntiles = (nrows + TR - 1) / TR;
    int stride = gridDim.x;

    uint4 reg[8];

    // prologue: tile blockIdx.x -> Xs0 (2048 uint4, 8 per thread)
    {
        long long r0 = (long long)blockIdx.x * TR;
#pragma unroll
        for (int p = 0; p < 8; p++) {
            int idx = tid + 256 * p;
            long long gr = r0 + (idx >> 4);
            reg[p] = (gr < nrows) ? __ldg((const uint4*)in + gr * 16 + (idx & 15))
                                  : make_uint4(0, 0, 0, 0);
        }
#pragma unroll
        for (int p = 0; p < 8; p++) {
            int idx = tid + 256 * p;
            *(uint4*)(Xs0 + (idx >> 4) * XSTR + (idx & 15) * 8) = reg[p];
        }
    }
    __syncthreads();

    unsigned xbase[2] = {xs0_base, xs1_base};
    __half* bufs[2] = {Xs0, Xs1};
    int buf = 0;

    for (int tt = blockIdx.x; tt < ntiles; tt += stride) {
        int nxt = tt + stride;
        if (nxt < ntiles) {
            long long r0 = (long long)nxt * TR;
#pragma unroll
            for (int p = 0; p < 8; p++) {
                int idx = tid + 256 * p;
                long long gr = r0 + (idx >> 4);
                reg[p] = (gr < nrows) ? __ldg((const uint4*)in + gr * 16 + (idx & 15))
                                      : make_uint4(0, 0, 0, 0);
            }
        }

        unsigned xs = xbase[buf];

        // ---- MMA1: T[16 rows][128 cols] ----
        float acc1[16][4];
#pragma unroll
        for (int j = 0; j < 16; j++)
#pragma unroll
            for (int q = 0; q < 4; q++) acc1[j][q] = 0.f;

#pragma unroll
        for (int kk = 0; kk < 8; kk++) {
            int k0 = kk * 16;
            unsigned a[4];
            ldsm_x4(a[0], a[1], a[2], a[3], xs + a_off + k0 * 2);
#pragma unroll
            for (int j = 0; j < 16; j += 2) {
                unsigned r0, r1, r2, r3;
                ldsm_x4(r0, r1, r2, r3,
                        ws1_base + b1_off + (j * 8 * WSTR + k0) * 2);
                unsigned bj0[2] = {r0, r1};
                unsigned bj1[2] = {r2, r3};
                mma_16x8x16(acc1[j], a, bj0);
                mma_16x8x16(acc1[j + 1], a, bj1);
            }
        }

        // ---- bias1 + relu + convert: C-frag -> A-frag (af) ----
        unsigned af[16][2];
#pragma unroll
        for (int j = 0; j < 16; j++) {
            int c0 = j * 8 + 2 * ti;
            float2 bb = __ldg((const float2*)(b1 + c0));
            float v0 = fmaxf(acc1[j][0] + bb.x, 0.f);
            float v1 = fmaxf(acc1[j][1] + bb.y, 0.f);
            float v2 = fmaxf(acc1[j][2] + bb.x, 0.f);
            float v3 = fmaxf(acc1[j][3] + bb.y, 0.f);
            __half2 lo = __floats2half2_rn(v0, v1);
            __half2 hi = __floats2half2_rn(v2, v3);
            af[j][0] = *(unsigned*)&lo;
            af[j][1] = *(unsigned*)&hi;
        }

        // ---- MMA2: out = T @ W2^T ----
        float acc2[16][4];
#pragma unroll
        for (int j = 0; j < 16; j++)
#pragma unroll
            for (int q = 0; q < 4; q++) acc2[j][q] = 0.f;

#pragma unroll
        for (int kk = 0; kk < 8; kk++) {
            int k0 = kk * 16;
            unsigned a[4] = {af[2 * kk][0], af[2 * kk][1],
                             af[2 * kk + 1][0], af[2 * kk + 1][1]};
#pragma unroll
            for (int j = 0; j < 16; j += 2) {
                unsigned r0, r1, r2, r3;
                ldsm_x4(r0, r1, r2, r3,
                        ws2_base + b1_off + (j * 8 * WSTR + k0) * 2);
                unsigned bj0[2] = {r0, r1};
                unsigned bj1[2] = {r2, r3};
                mma_16x8x16(acc2[j], a, bj0);
                mma_16x8x16(acc2[j + 1], a, bj1);
            }
        }

        // ---- epilogue: bias2, store ----
        long long row0 = (long long)tt * TR + mbase + gi;
#pragma unroll
        for (int j = 0; j < 16; j++) {
            int c0 = j * 8 + 2 * ti;
            float2 bb = __ldg((const float2*)(b2 + c0));
            float v0 = acc2[j][0] + bb.x;
            float v1 = acc2[j][1] + bb.y;
            float v2 = acc2[j][2] + bb.x;
            float v3 = acc2[j][3] + bb.y;
            if (outf) {
                if (row0 < nrows)
                    *(float2*)(outf + row0 * D + c0) = make_float2(v0, v1);
                if (row0 + 8 < nrows)
                    *(float2*)(outf + (row0 + 8) * D + c0) = make_float2(v2, v3);
            } else {
                if (row0 < nrows)
                    *(__half2*)(outh + row0 * D + c0) = __floats2half2_rn(v0, v1);
                if (row0 + 8 < nrows)
                    *(__half2*)(outh + (row0 + 8) * D + c0) = __floats2half2_rn(v2, v3);
            }
        }

        if (nxt < ntiles) {
#pragma unroll
            for (int p = 0; p < 8; p++) {
                int idx = tid + 256 * p;
                *(uint4*)(bufs[buf ^ 1] + (idx >> 4) * XSTR + (idx & 15) * 8) = reg[p];
            }
            __syncthreads();
            buf ^= 1;
        }
    }
}

// ---------------------------------------------------------------------------
extern "C" void kernel_launch(void* const* d_in, const int* in_sizes, int n_in,
                              void* d_out, int out_size) {
    const float* x   = (const float*)d_in[0];
    const int*   ei  = (const int*)d_in[1];
    const float* w0a = (const float*)d_in[2];
    const float* b0a = (const float*)d_in[3];
    const float* w0b = (const float*)d_in[4];
    const float* b0b = (const float*)d_in[5];
    const float* w1a = (const float*)d_in[6];
    const float* b1a = (const float*)d_in[7];
    const float* w1b = (const float*)d_in[8];
    const float* b1b = (const float*)d_in[9];

    int N = in_sizes[0] / D;
    int E = in_sizes[1] / 2;

    __half *p_xh, *p_hh, *p_oh, *p_wh;
    cudaGetSymbolAddress((void**)&p_xh, g_xh);
    cudaGetSymbolAddress((void**)&p_hh, g_hh);
    cudaGetSymbolAddress((void**)&p_oh, g_oh);
    cudaGetSymbolAddress((void**)&p_wh, g_wh);

    int nsm = 148;
    cudaDeviceGetAttribute(&nsm, cudaDevAttrMultiProcessorCount, 0);

    const int smem = (2 * 128 * WSTR + 2 * TR * XSTR) * (int)sizeof(__half);
    cudaFuncSetAttribute(layer_fused_kernel, cudaFuncAttributeMaxDynamicSharedMemorySize, smem);

    int nb = (N + 1023) / 1024;
    int gatherBlocks = (N + 7) / 8;
    int n4 = N * (D / 4);
    int e4 = (E + 3) / 4;

    convert_w_kernel<<<(4 * D * D + 255) / 256, 256>>>(w0a, w0b, w1a, w1b);
    convert_x_kernel<<<(n4 + 255) / 256, 256>>>(x, n4);

    // ---- CSR build ----
    zero_deg_kernel<<<(N + 255) / 256, 256>>>(N);
    hist_kernel<<<(e4 + 255) / 256, 256>>>(ei, E);
    scan1_kernel<<<nb, 1024>>>(N);
    scan2_kernel<<<1, 128>>>(nb);
    scan3_kernel<<<(N + 255) / 256, 256>>>(N, E);
    fill_kernel<<<(e4 + 255) / 256, 256>>>(ei, E);

    // ---- Layer 1 ----
    gather_h_kernel<<<gatherBlocks, 256>>>(p_xh, p_hh, N);
    layer_fused_kernel<<<nsm, 256, smem>>>(p_hh, p_wh + 0 * D * D, b0a,
                                           p_wh + 1 * D * D, b0b, p_oh, nullptr, N);

    // ---- Layer 2 ----
    gather_h_kernel<<<gatherBlocks, 256>>>(p_oh, p_hh, N);
    layer_fused_kernel<<<nsm, 256, smem>>>(p_hh, p_wh + 2 * D * D, b1a,
                                           p_wh + 3 * D * D, b1b, nullptr, (float*)d_out, N);
}

// round 9
// speedup vs baseline: 3.2437x; 1.1301x over previous
#include <cuda_runtime.h>
#include <cuda_fp16.h>
#include <cstdint>

#define D 128
#define MAXN 100000
#define MAXE 1600000

// Scratch (allocation-free rule: __device__ globals) — fp16 activations
__device__ __align__(16) __half g_xh[(size_t)MAXN * D];
__device__ __align__(16) __half g_hh[(size_t)MAXN * D];
__device__ __align__(16) __half g_oh[(size_t)MAXN * D];
__device__ __align__(16) __half g_wh[4 * D * D];   // weights [c][k] fp16
__device__ int g_deg[MAXN];
__device__ int g_incl[MAXN];
__device__ int g_bsum[128];
__device__ int g_rowptr[MAXN + 1];
__device__ int g_cursor[MAXN];
__device__ int g_elist[MAXE];

// ---------------------------------------------------------------------------
// prep: convert 4 weights to fp16, convert x to fp16, zero deg — one launch.
__global__ void prep_kernel(const float* __restrict__ x,
                            const float* __restrict__ w0,
                            const float* __restrict__ w1,
                            const float* __restrict__ w2,
                            const float* __restrict__ w3,
                            int n4, int n) {
    int i = blockIdx.x * blockDim.x + threadIdx.x;
    if (i < 4 * D * D) {
        int widx = i >> 14;
        const float* w = (widx == 0) ? w0 : (widx == 1) ? w1 : (widx == 2) ? w2 : w3;
        g_wh[i] = __float2half(w[i & 16383]);
    }
    int j = i - 4 * D * D;
    if (j >= 0 && j < n4) {
        float4 v = __ldg((const float4*)x + j);
        __half2 h0 = __floats2half2_rn(v.x, v.y);
        __half2 h1 = __floats2half2_rn(v.z, v.w);
        uint2 u;
        u.x = *(unsigned*)&h0;
        u.y = *(unsigned*)&h1;
        ((uint2*)g_xh)[j] = u;
    }
    int k = j - n4;
    if (k >= 0 && k < n) g_deg[k] = 0;
}

// ---------------------------------------------------------------------------
// CSR build
__global__ void hist_kernel(const int* __restrict__ ei, int E) {
    int t = blockIdx.x * blockDim.x + threadIdx.x;
    int base = t * 4;
    if (base + 4 <= E) {
        int4 d = __ldg((const int4*)(ei + E) + t);
        atomicAdd(&g_deg[d.x], 1);
        atomicAdd(&g_deg[d.y], 1);
        atomicAdd(&g_deg[d.z], 1);
        atomicAdd(&g_deg[d.w], 1);
    } else {
        for (int e = base; e < E; e++) atomicAdd(&g_deg[__ldg(ei + E + e)], 1);
    }
}

__global__ void scan1_kernel(int n) {
    __shared__ int wsum[32];
    int t = threadIdx.x, b = blockIdx.x;
    int i = b * 1024 + t;
    int lane = t & 31, warp = t >> 5;
    int v = (i < n) ? g_deg[i] : 0;
    int s = v;
#pragma unroll
    for (int off = 1; off < 32; off <<= 1) {
        int u = __shfl_up_sync(0xffffffffu, s, off);
        if (lane >= off) s += u;
    }
    if (lane == 31) wsum[warp] = s;
    __syncthreads();
    if (warp == 0) {
        int ws = wsum[lane];
#pragma unroll
        for (int off = 1; off < 32; off <<= 1) {
            int u = __shfl_up_sync(0xffffffffu, ws, off);
            if (lane >= off) ws += u;
        }
        wsum[lane] = ws;
    }
    __syncthreads();
    int incl = s + (warp > 0 ? wsum[warp - 1] : 0);
    if (i < n) g_incl[i] = incl;
    if (t == 1023) g_bsum[b] = incl;
}

// scan2+scan3 merged: each block computes its own bsum prefix (warp sum).
__global__ void scan23_kernel(int n, int E) {
    __shared__ int pre;
    int t = threadIdx.x, b = blockIdx.x;
    if (t < 32) {
        int s = 0;
        for (int j = t; j < b; j += 32) s += g_bsum[j];
#pragma unroll
        for (int off = 16; off; off >>= 1)
            s += __shfl_down_sync(0xffffffffu, s, off);
        if (t == 0) pre = s;
    }
    __syncthreads();
    int i = b * 1024 + t;
    if (i < n) {
        int excl = pre + g_incl[i] - g_deg[i];
        g_rowptr[i] = excl;
        g_cursor[i] = excl;
    }
    if (i == 0) g_rowptr[n] = E;
}

__global__ void fill_kernel(const int* __restrict__ ei, int E) {
    int t = blockIdx.x * blockDim.x + threadIdx.x;
    int base = t * 4;
    if (base + 4 <= E) {
        int4 s = __ldg((const int4*)ei + t);
        int4 d = __ldg((const int4*)(ei + E) + t);
        g_elist[atomicAdd(&g_cursor[d.x], 1)] = s.x;
        g_elist[atomicAdd(&g_cursor[d.y], 1)] = s.y;
        g_elist[atomicAdd(&g_cursor[d.z], 1)] = s.z;
        g_elist[atomicAdd(&g_cursor[d.w], 1)] = s.w;
    } else {
        for (int e = base; e < E; e++) {
            int s = __ldg(ei + e);
            int d = __ldg(ei + E + e);
            g_elist[atomicAdd(&g_cursor[d], 1)] = s;
        }
    }
}

// ---------------------------------------------------------------------------
// Gather: h[n] = x[n] + sum_{s in N(n)} x[s].  fp16 in/out, fp32 accumulate.
__device__ __forceinline__ void acc_add(float4& a, uint2 u) {
    float2 f0 = __half22float2(*(__half2*)&u.x);
    float2 f1 = __half22float2(*(__half2*)&u.y);
    a.x += f0.x; a.y += f0.y; a.z += f1.x; a.w += f1.y;
}

__global__ void gather_h_kernel(const __half* __restrict__ xin,
                                __half* __restrict__ hout, int N) {
    int w = (int)((blockIdx.x * (unsigned)blockDim.x + threadIdx.x) >> 5);
    if (w >= N) return;
    int lane = threadIdx.x & 31;
    const uint2* x2 = (const uint2*)xin;
    float4 acc = make_float4(0.f, 0.f, 0.f, 0.f);
    acc_add(acc, __ldg(x2 + (long long)w * 32 + lane));
    int beg = __ldg(g_rowptr + w);
    int end = __ldg(g_rowptr + w + 1);
    int i = beg;
    for (; i + 4 <= end; i += 4) {
        int s0 = __ldg(g_elist + i);
        int s1 = __ldg(g_elist + i + 1);
        int s2 = __ldg(g_elist + i + 2);
        int s3 = __ldg(g_elist + i + 3);
        uint2 v0 = __ldg(x2 + (long long)s0 * 32 + lane);
        uint2 v1 = __ldg(x2 + (long long)s1 * 32 + lane);
        uint2 v2 = __ldg(x2 + (long long)s2 * 32 + lane);
        uint2 v3 = __ldg(x2 + (long long)s3 * 32 + lane);
        acc_add(acc, v0); acc_add(acc, v1); acc_add(acc, v2); acc_add(acc, v3);
    }
    for (; i < end; i++) {
        int s0 = __ldg(g_elist + i);
        acc_add(acc, __ldg(x2 + (long long)s0 * 32 + lane));
    }
    __half2 h0 = __floats2half2_rn(acc.x, acc.y);
    __half2 h1 = __floats2half2_rn(acc.z, acc.w);
    uint2 u;
    u.x = *(unsigned*)&h0;
    u.y = *(unsigned*)&h1;
    ((uint2*)hout)[(long long)w * 32 + lane] = u;
}

// ---------------------------------------------------------------------------
// Fused layer: out = relu(X @ W1^T + b1) @ W2^T + b2   (persistent, fp16 MMA)
// Tile 128 rows; each warp owns a 16-row stripe, all 128 cols.
// T never leaves registers (C-frag == A-frag). Fragment loads via ldmatrix.
// Biases staged in smem once.
#define XSTR 136
#define WSTR 136
#define TR 128

__device__ __forceinline__ void mma_16x8x16(float* d, const unsigned* a, const unsigned* b) {
    asm volatile(
        "mma.sync.aligned.m16n8k16.row.col.f32.f16.f16.f32 "
        "{%0,%1,%2,%3}, {%4,%5,%6,%7}, {%8,%9}, {%0,%1,%2,%3};"
        : "+f"(d[0]), "+f"(d[1]), "+f"(d[2]), "+f"(d[3])
        : "r"(a[0]), "r"(a[1]), "r"(a[2]), "r"(a[3]), "r"(b[0]), "r"(b[1]));
}

__device__ __forceinline__ void ldsm_x4(unsigned& r0, unsigned& r1,
                                        unsigned& r2, unsigned& r3, unsigned addr) {
    asm volatile("ldmatrix.sync.aligned.m8n8.x4.shared.b16 {%0,%1,%2,%3}, [%4];"
                 : "=r"(r0), "=r"(r1), "=r"(r2), "=r"(r3) : "r"(addr));
}

__global__ __launch_bounds__(256, 1)
void layer_fused_kernel(const __half* __restrict__ in,
                        const __half* __restrict__ w1,   // [c][k]
                        const float* __restrict__ b1,
                        const __half* __restrict__ w2,   // [c][k]
                        const float* __restrict__ b2,
                        __half* __restrict__ outh,
                        float* __restrict__ outf,
                        int nrows) {
    extern __shared__ __half smh[];
    __half* Ws1 = smh;                        // [128][WSTR]
    __half* Ws2 = smh + 128 * WSTR;           // [128][WSTR]
    __half* Xs0 = smh + 2 * 128 * WSTR;       // [128][XSTR]
    __half* Xs1 = Xs0 + TR * XSTR;
    float*  Bs1 = (float*)(Xs1 + TR * XSTR);  // [128]
    float*  Bs2 = Bs1 + 128;                  // [128]

    int tid = threadIdx.x;

    // Load both W panels (each 128 rows x 16 uint4) + biases
    for (int i = tid; i < 128 * 16; i += 256) {
        int c = i >> 4, seg = i & 15;
        *(uint4*)(Ws1 + c * WSTR + seg * 8) = __ldg((const uint4*)w1 + i);
        *(uint4*)(Ws2 + c * WSTR + seg * 8) = __ldg((const uint4*)w2 + i);
    }
    if (tid < 128) {
        Bs1[tid] = __ldg(b1 + tid);
        Bs2[tid] = __ldg(b2 + tid);
    }

    int warp = tid >> 5, lane = tid & 31;
    int gi = lane >> 2, ti = lane & 3;
    int mbase = warp * 16;

    // ldmatrix per-lane address offsets
    int a_row = mbase + (lane & 7) + (((lane >> 3) & 1) << 3);
    int a_koff = (lane >> 4) << 3;
    int b_row = (lane & 7) + ((lane >> 4) << 3);
    int b_koff = ((lane >> 3) & 1) << 3;

    unsigned ws1_base = (unsigned)__cvta_generic_to_shared(Ws1);
    unsigned ws2_base = (unsigned)__cvta_generic_to_shared(Ws2);
    unsigned xs0_base = (unsigned)__cvta_generic_to_shared(Xs0);
    unsigned xs1_base = (unsigned)__cvta_generic_to_shared(Xs1);
    unsigned b1_off = (b_row * WSTR + b_koff) * 2;
    unsigned a_off  = (a_row * XSTR + a_koff) * 2;

    int ntiles = (nrows + TR - 1) / TR;
    int stride = gridDim.x;

    uint4 reg[8];

    // prologue: tile blockIdx.x -> Xs0
    {
        long long r0 = (long long)blockIdx.x * TR;
#pragma unroll
        for (int p = 0; p < 8; p++) {
            int idx = tid + 256 * p;
            long long gr = r0 + (idx >> 4);
            reg[p] = (gr < nrows) ? __ldg((const uint4*)in + gr * 16 + (idx & 15))
                                  : make_uint4(0, 0, 0, 0);
        }
#pragma unroll
        for (int p = 0; p < 8; p++) {
            int idx = tid + 256 * p;
            *(uint4*)(Xs0 + (idx >> 4) * XSTR + (idx & 15) * 8) = reg[p];
        }
    }
    __syncthreads();

    unsigned xbase[2] = {xs0_base, xs1_base};
    __half* bufs[2] = {Xs0, Xs1};
    int buf = 0;

    for (int tt = blockIdx.x; tt < ntiles; tt += stride) {
        int nxt = tt + stride;
        if (nxt < ntiles) {
            long long r0 = (long long)nxt * TR;
#pragma unroll
            for (int p = 0; p < 8; p++) {
                int idx = tid + 256 * p;
                long long gr = r0 + (idx >> 4);
                reg[p] = (gr < nrows) ? __ldg((const uint4*)in + gr * 16 + (idx & 15))
                                      : make_uint4(0, 0, 0, 0);
            }
        }

        unsigned xs = xbase[buf];

        // ---- MMA1: T[16 rows][128 cols] ----
        float acc1[16][4];
#pragma unroll
        for (int j = 0; j < 16; j++)
#pragma unroll
            for (int q = 0; q < 4; q++) acc1[j][q] = 0.f;

#pragma unroll
        for (int kk = 0; kk < 8; kk++) {
            int k0 = kk * 16;
            unsigned a[4];
            ldsm_x4(a[0], a[1], a[2], a[3], xs + a_off + k0 * 2);
#pragma unroll
            for (int j = 0; j < 16; j += 2) {
                unsigned r0, r1, r2, r3;
                ldsm_x4(r0, r1, r2, r3,
                        ws1_base + b1_off + (j * 8 * WSTR + k0) * 2);
                unsigned bj0[2] = {r0, r1};
                unsigned bj1[2] = {r2, r3};
                mma_16x8x16(acc1[j], a, bj0);
                mma_16x8x16(acc1[j + 1], a, bj1);
            }
        }

        // ---- bias1 + relu + convert: C-frag -> A-frag (af) ----
        unsigned af[16][2];
#pragma unroll
        for (int j = 0; j < 16; j++) {
            int c0 = j * 8 + 2 * ti;
            float bx = Bs1[c0], by = Bs1[c0 + 1];
            float v0 = fmaxf(acc1[j][0] + bx, 0.f);
            float v1 = fmaxf(acc1[j][1] + by, 0.f);
            float v2 = fmaxf(acc1[j][2] + bx, 0.f);
            float v3 = fmaxf(acc1[j][3] + by, 0.f);
            __half2 lo = __floats2half2_rn(v0, v1);
            __half2 hi = __floats2half2_rn(v2, v3);
            af[j][0] = *(unsigned*)&lo;
            af[j][1] = *(unsigned*)&hi;
        }

        // ---- MMA2: out = T @ W2^T ----
        float acc2[16][4];
#pragma unroll
        for (int j = 0; j < 16; j++)
#pragma unroll
            for (int q = 0; q < 4; q++) acc2[j][q] = 0.f;

#pragma unroll
        for (int kk = 0; kk < 8; kk++) {
            int k0 = kk * 16;
            unsigned a[4] = {af[2 * kk][0], af[2 * kk][1],
                             af[2 * kk + 1][0], af[2 * kk + 1][1]};
#pragma unroll
            for (int j = 0; j < 16; j += 2) {
                unsigned r0, r1, r2, r3;
                ldsm_x4(r0, r1, r2, r3,
                        ws2_base + b1_off + (j * 8 * WSTR + k0) * 2);
                unsigned bj0[2] = {r0, r1};
                unsigned bj1[2] = {r2, r3};
                mma_16x8x16(acc2[j], a, bj0);
                mma_16x8x16(acc2[j + 1], a, bj1);
            }
        }

        // ---- epilogue: bias2, store ----
        long long row0 = (long long)tt * TR + mbase + gi;
#pragma unroll
        for (int j = 0; j < 16; j++) {
            int c0 = j * 8 + 2 * ti;
            float bx = Bs2[c0], by = Bs2[c0 + 1];
            float v0 = acc2[j][0] + bx;
            float v1 = acc2[j][1] + by;
            float v2 = acc2[j][2] + bx;
            float v3 = acc2[j][3] + by;
            if (outf) {
                if (row0 < nrows)
                    *(float2*)(outf + row0 * D + c0) = make_float2(v0, v1);
                if (row0 + 8 < nrows)
                    *(float2*)(outf + (row0 + 8) * D + c0) = make_float2(v2, v3);
            } else {
                if (row0 < nrows)
                    *(__half2*)(outh + row0 * D + c0) = __floats2half2_rn(v0, v1);
                if (row0 + 8 < nrows)
                    *(__half2*)(outh + (row0 + 8) * D + c0) = __floats2half2_rn(v2, v3);
            }
        }

        if (nxt < ntiles) {
#pragma unroll
            for (int p = 0; p < 8; p++) {
                int idx = tid + 256 * p;
                *(uint4*)(bufs[buf ^ 1] + (idx >> 4) * XSTR + (idx & 15) * 8) = reg[p];
            }
            __syncthreads();
            buf ^= 1;
        }
    }
}

// ---------------------------------------------------------------------------
extern "C" void kernel_launch(void* const* d_in, const int* in_sizes, int n_in,
                              void* d_out, int out_size) {
    const float* x   = (const float*)d_in[0];
    const int*   ei  = (const int*)d_in[1];
    const float* w0a = (const float*)d_in[2];
    const float* b0a = (const float*)d_in[3];
    const float* w0b = (const float*)d_in[4];
    const float* b0b = (const float*)d_in[5];
    const float* w1a = (const float*)d_in[6];
    const float* b1a = (const float*)d_in[7];
    const float* w1b = (const float*)d_in[8];
    const float* b1b = (const float*)d_in[9];

    int N = in_sizes[0] / D;
    int E = in_sizes[1] / 2;

    __half *p_xh, *p_hh, *p_oh, *p_wh;
    cudaGetSymbolAddress((void**)&p_xh, g_xh);
    cudaGetSymbolAddress((void**)&p_hh, g_hh);
    cudaGetSymbolAddress((void**)&p_oh, g_oh);
    cudaGetSymbolAddress((void**)&p_wh, g_wh);

    int nsm = 148;
    cudaDeviceGetAttribute(&nsm, cudaDevAttrMultiProcessorCount, 0);

    const int smem = (2 * 128 * WSTR + 2 * TR * XSTR) * (int)sizeof(__half)
                   + 256 * (int)sizeof(float);
    cudaFuncSetAttribute(layer_fused_kernel, cudaFuncAttributeMaxDynamicSharedMemorySize, smem);

    int nb = (N + 1023) / 1024;
    int gatherBlocks = (N + 7) / 8;
    int n4 = N * (D / 4);
    int e4 = (E + 3) / 4;
    int prepTotal = 4 * D * D + n4 + N;

    prep_kernel<<<(prepTotal + 255) / 256, 256>>>(x, w0a, w0b, w1a, w1b, n4, N);

    // ---- CSR build ----
    hist_kernel<<<(e4 + 255) / 256, 256>>>(ei, E);
    scan1_kernel<<<nb, 1024>>>(N);
    scan23_kernel<<<nb, 1024>>>(N, E);
    fill_kernel<<<(e4 + 255) / 256, 256>>>(ei, E);

    // ---- Layer 1 ----
    gather_h_kernel<<<gatherBlocks, 256>>>(p_xh, p_hh, N);
    layer_fused_kernel<<<nsm, 256, smem>>>(p_hh, p_wh + 0 * D * D, b0a,
                                           p_wh + 1 * D * D, b0b, p_oh, nullptr, N);

    // ---- Layer 2 ----
    gather_h_kernel<<<gatherBlocks, 256>>>(p_oh, p_hh, N);
    layer_fused_kernel<<<nsm, 256, smem>>>(p_hh, p_wh + 2 * D * D, b1a,
                                           p_wh + 3 * D * D, b1b, nullptr, (float*)d_out, N);
}